// round 14
// baseline (speedup 1.0000x reference)
#include <cuda_runtime.h>
#include <cuda_fp16.h>
#include <math.h>
#include <stdint.h>

// Problem constants
#define NB     64
#define DIM    64
#define HW     1024
#define NTOK   65536         // NB*HW
#define KCODES 1024
#define ZQ_ELEMS 4194304     // NB*DIM*HW
#define CHUNK  64            // codes per smem chunk (argmin)
#define NCHUNKS (KCODES / CHUNK)   // 16
#define EPS    0.065f

// ---------------------------------------------------------------------------
// Device global scratch (no allocation allowed)
// ---------------------------------------------------------------------------
__device__ __align__(16) uint2 g_cbf[NCHUNKS * 8 * 4 * 32];   // fp16 fragments, 128 KB
__device__ __align__(16) float g_cnorm[KCODES];
__device__ int   g_idx[NTOK];
__device__ int   g_rescue[NTOK];       // full-scan rescue list (3-way ambiguous)
__device__ int   g_rescue_cnt;
__device__ int   g_pair[NTOK];         // pair-rescue list (2-way ambiguous)
__device__ int2  g_pairc[NTOK];        // candidate indices {i1, i2}
__device__ float g_pairn[NTOK];        // exact ||z||^2
__device__ int   g_pair_cnt;
__device__ float g_losssum;
__device__ int   g_hist[KCODES];

// ---------------------------------------------------------------------------
// Helpers
// ---------------------------------------------------------------------------
__device__ __forceinline__ void mma16816_f16(float* c, const uint32_t* a,
                                             uint32_t b0, uint32_t b1) {
    asm volatile(
        "mma.sync.aligned.m16n8k16.row.col.f32.f16.f16.f32 "
        "{%0,%1,%2,%3}, {%4,%5,%6,%7}, {%8,%9}, {%0,%1,%2,%3};"
        : "+f"(c[0]), "+f"(c[1]), "+f"(c[2]), "+f"(c[3])
        : "r"(a[0]), "r"(a[1]), "r"(a[2]), "r"(a[3]), "r"(b0), "r"(b1));
}
__device__ __forceinline__ uint32_t pack_h2(float v0, float v1) {
    __half2 h = __floats2half2_rn(v0, v1);
    return *(uint32_t*)&h;
}
__device__ __forceinline__ uint32_t smem_u32(const void* p) {
    uint32_t a;
    asm("{ .reg .u64 t; cvta.to.shared.u64 t, %1; cvt.u32.u64 %0, t; }"
        : "=r"(a) : "l"(p));
    return a;
}
__device__ __forceinline__ void cp16(uint32_t dst, const void* src) {
    asm volatile("cp.async.cg.shared.global [%0], [%1], 16;"
                 :: "r"(dst), "l"(src));
}
#define CP_COMMIT() asm volatile("cp.async.commit_group;" ::: "memory")
#define CP_WAIT0()  asm volatile("cp.async.wait_group 0;" ::: "memory")

// top-3 tracker (strict < and ascending code order -> first-occurrence ties)
__device__ __forceinline__ void upd3(float s, int code,
                                     float& s1, int& i1,
                                     float& s2, int& i2, float& s3) {
    if (s < s3) {
        if (s < s2) {
            s3 = s2;
            if (s < s1) { s2 = s1; i2 = i1; s1 = s; i1 = code; }
            else        { s2 = s;  i2 = code; }
        } else s3 = s;
    }
}
__device__ __forceinline__ bool lexless(float v, int i, float w, int j) {
    return v < w || (v == w && i < j);
}

// ---------------------------------------------------------------------------
// Prep: fp16 fragment codebook, ||c||^2, zero counters
// ---------------------------------------------------------------------------
__global__ void prep_kernel(const float* __restrict__ cb) {
    int k = blockIdx.x * blockDim.x + threadIdx.x;
    if (k >= KCODES) return;
    float v[DIM];
    float s = 0.f;
#pragma unroll
    for (int c = 0; c < DIM; ++c) {
        v[c] = cb[k * DIM + c];
        s = fmaf(v[c], v[c], s);
    }
    g_cnorm[k] = s;
    g_hist[k]  = 0;
    if (k == 0) { g_losssum = 0.f; g_rescue_cnt = 0; g_pair_cnt = 0; }

    const int chunk = k >> 6;
    const int n8    = (k & 63) >> 3;
    const int g     = k & 7;
#pragma unroll
    for (int ks = 0; ks < 4; ++ks) {
#pragma unroll
        for (int t4 = 0; t4 < 4; ++t4) {
            int d0 = ks * 16 + t4 * 2;
            int idx = ((chunk * 8 + n8) * 4 + ks) * 32 + g * 4 + t4;
            g_cbf[idx] = make_uint2(pack_h2(v[d0],     v[d0 + 1]),
                                    pack_h2(v[d0 + 8], v[d0 + 9]));
        }
    }
}

// ---------------------------------------------------------------------------
// fp16 HMMA argmin: 8 warps x 16 tokens; 1-term fp16 mma.sync (fp32 accum).
// Tracks top-3 (+ ||z||^2). Unflagged -> hist/loss here. 2-way ambiguous ->
// pair rescue {i1,i2}. 3-way ambiguous -> full-scan rescue.
// ---------------------------------------------------------------------------
#define SMCN_F   0
#define SMBUF(b) (4096 + (b) * 8192)
#define SM_BYTES (4096 + 2 * 8192)

__global__ void __launch_bounds__(256) argmin_mma_kernel(const float* __restrict__ z) {
    __shared__ __align__(16) char smem[SM_BYTES];
    const uint32_t smb = smem_u32(smem);
    const int tid  = threadIdx.x;
    const int wid  = tid >> 5;
    const int lane = tid & 31;
    const int g    = lane >> 2;
    const int t4   = lane & 3;

    {
        float4* dst = (float4*)(smem + SMCN_F);
        const float4* src = (const float4*)g_cnorm;
        dst[tid] = src[tid];
    }

    const int wbase = blockIdx.x * 128 + wid * 16;
    const int b     = wbase >> 10;
    const int hw0   = (wbase & (HW - 1)) + g;
    const float* zb = z + b * (DIM * HW);
    uint32_t Ah[16];
    float n0 = 0.f, n1 = 0.f;        // partial ||z||^2 for tokens g, g+8
#pragma unroll
    for (int ks = 0; ks < 4; ++ks) {
        int c0 = ks * 16 + t4 * 2;
        float a0 = zb[(c0)     * HW + hw0],     a1 = zb[(c0 + 1) * HW + hw0];
        float b0 = zb[(c0)     * HW + hw0 + 8], b1 = zb[(c0 + 1) * HW + hw0 + 8];
        float a2 = zb[(c0 + 8) * HW + hw0],     a3 = zb[(c0 + 9) * HW + hw0];
        float b2 = zb[(c0 + 8) * HW + hw0 + 8], b3 = zb[(c0 + 9) * HW + hw0 + 8];
        n0 = fmaf(a0, a0, n0); n0 = fmaf(a1, a1, n0);
        n0 = fmaf(a2, a2, n0); n0 = fmaf(a3, a3, n0);
        n1 = fmaf(b0, b0, n1); n1 = fmaf(b1, b1, n1);
        n1 = fmaf(b2, b2, n1); n1 = fmaf(b3, b3, n1);
        Ah[ks * 4 + 0] = pack_h2(a0, a1);
        Ah[ks * 4 + 1] = pack_h2(b0, b1);
        Ah[ks * 4 + 2] = pack_h2(a2, a3);
        Ah[ks * 4 + 3] = pack_h2(b2, b3);
    }

    {
        const char* src = (const char*)g_cbf;
        uint32_t d = smb + SMBUF(0);
#pragma unroll
        for (int i = 0; i < 2; ++i)
            cp16(d + tid * 16 + i * 4096, src + tid * 16 + i * 4096);
        CP_COMMIT();
    }

    float s1a = 3.4e38f, s2a = 3.4e38f, s3a = 3.4e38f; int i1a = 0, i2a = 0;
    float s1b = 3.4e38f, s2b = 3.4e38f, s3b = 3.4e38f; int i1b = 0, i2b = 0;

    for (int t = 0; t < NCHUNKS; ++t) {
        const int buf = t & 1;
        CP_WAIT0();
        __syncthreads();

        if (t + 1 < NCHUNKS) {
            const char* src = (const char*)g_cbf + (t + 1) * 8192;
            uint32_t d = smb + SMBUF(1 - buf);
#pragma unroll
            for (int i = 0; i < 2; ++i)
                cp16(d + tid * 16 + i * 4096, src + tid * 16 + i * 4096);
            CP_COMMIT();
        }

        const uint2* bq = (const uint2*)(smem + SMBUF(buf));
        const float* cn = (const float*)(smem + SMCN_F);

#pragma unroll
        for (int n8 = 0; n8 < 8; ++n8) {
            uint2 Bf[4];
#pragma unroll
            for (int ks = 0; ks < 4; ++ks)
                Bf[ks] = bq[(n8 * 4 + ks) * 32 + lane];
            float ae[4] = {0.f, 0.f, 0.f, 0.f};
            float ao[4] = {0.f, 0.f, 0.f, 0.f};
            mma16816_f16(ae, &Ah[0],  Bf[0].x, Bf[0].y);
            mma16816_f16(ao, &Ah[4],  Bf[1].x, Bf[1].y);
            mma16816_f16(ae, &Ah[8],  Bf[2].x, Bf[2].y);
            mma16816_f16(ao, &Ah[12], Bf[3].x, Bf[3].y);

            const int code = t * CHUNK + n8 * 8 + t4 * 2;
            float2 cnv = *(const float2*)(cn + code);
            float s;
            s = fmaf(-2.f, ae[0] + ao[0], cnv.x); upd3(s, code,     s1a, i1a, s2a, i2a, s3a);
            s = fmaf(-2.f, ae[1] + ao[1], cnv.y); upd3(s, code + 1, s1a, i1a, s2a, i2a, s3a);
            s = fmaf(-2.f, ae[2] + ao[2], cnv.x); upd3(s, code,     s1b, i1b, s2b, i2b, s3b);
            s = fmaf(-2.f, ae[3] + ao[3], cnv.y); upd3(s, code + 1, s1b, i1b, s2b, i2b, s3b);
        }
        __syncthreads();
    }

    // Reduce top-3 (lex) and norms across the 4 lanes of each quad
#pragma unroll
    for (int off = 1; off <= 2; off <<= 1) {
        float ob1, ob2, ob3; int oj1, oj2;
        // token a
        ob1 = __shfl_xor_sync(0xffffffffu, s1a, off);
        ob2 = __shfl_xor_sync(0xffffffffu, s2a, off);
        ob3 = __shfl_xor_sync(0xffffffffu, s3a, off);
        oj1 = __shfl_xor_sync(0xffffffffu, i1a, off);
        oj2 = __shfl_xor_sync(0xffffffffu, i2a, off);
        {
            float r1, r2, r3; int q1, q2;
            if (lexless(ob1, oj1, s1a, i1a)) {
                r1 = ob1; q1 = oj1;
                if (lexless(s1a, i1a, ob2, oj2)) { r2 = s1a; q2 = i1a; r3 = fminf(s2a, ob2); }
                else                             { r2 = ob2; q2 = oj2; r3 = fminf(ob3, s1a); }
            } else {
                r1 = s1a; q1 = i1a;
                if (lexless(ob1, oj1, s2a, i2a)) { r2 = ob1; q2 = oj1; r3 = fminf(s2a, ob2); }
                else                             { r2 = s2a; q2 = i2a; r3 = fminf(s3a, ob1); }
            }
            s1a = r1; i1a = q1; s2a = r2; i2a = q2; s3a = r3;
        }
        // token b
        ob1 = __shfl_xor_sync(0xffffffffu, s1b, off);
        ob2 = __shfl_xor_sync(0xffffffffu, s2b, off);
        ob3 = __shfl_xor_sync(0xffffffffu, s3b, off);
        oj1 = __shfl_xor_sync(0xffffffffu, i1b, off);
        oj2 = __shfl_xor_sync(0xffffffffu, i2b, off);
        {
            float r1, r2, r3; int q1, q2;
            if (lexless(ob1, oj1, s1b, i1b)) {
                r1 = ob1; q1 = oj1;
                if (lexless(s1b, i1b, ob2, oj2)) { r2 = s1b; q2 = i1b; r3 = fminf(s2b, ob2); }
                else                             { r2 = ob2; q2 = oj2; r3 = fminf(ob3, s1b); }
            } else {
                r1 = s1b; q1 = i1b;
                if (lexless(ob1, oj1, s2b, i2b)) { r2 = ob1; q2 = oj1; r3 = fminf(s2b, ob2); }
                else                             { r2 = s2b; q2 = i2b; r3 = fminf(s3b, ob1); }
            }
            s1b = r1; i1b = q1; s2b = r2; i2b = q2; s3b = r3;
        }
        n0 += __shfl_xor_sync(0xffffffffu, n0, off);
        n1 += __shfl_xor_sync(0xffffffffu, n1, off);
    }

    float contrib = 0.f;
    if (t4 == 0) {
        const int tok0 = wbase + g;
        const int tok1 = wbase + g + 8;
        if (s2a - s1a >= EPS) {
            g_idx[tok0] = i1a;
            atomicAdd(&g_hist[i1a], 1);
            contrib += n0 + s1a;
        } else if (s3a - s1a >= EPS) {
            int s = atomicAdd(&g_pair_cnt, 1);
            g_pair[s] = tok0; g_pairc[s] = make_int2(i1a, i2a); g_pairn[s] = n0;
        } else {
            int s = atomicAdd(&g_rescue_cnt, 1); g_rescue[s] = tok0;
        }
        if (s2b - s1b >= EPS) {
            g_idx[tok1] = i1b;
            atomicAdd(&g_hist[i1b], 1);
            contrib += n1 + s1b;
        } else if (s3b - s1b >= EPS) {
            int s = atomicAdd(&g_pair_cnt, 1);
            g_pair[s] = tok1; g_pairc[s] = make_int2(i1b, i2b); g_pairn[s] = n1;
        } else {
            int s = atomicAdd(&g_rescue_cnt, 1); g_rescue[s] = tok1;
        }
    }
#pragma unroll
    for (int o = 16; o > 0; o >>= 1)
        contrib += __shfl_down_sync(0xffffffffu, contrib, o);
    if (lane == 0) atomicAdd(&g_losssum, contrib);
}

// ---------------------------------------------------------------------------
// Pair rescue: exact fp32 scoring of 2 candidate codes; one warp per token.
// ---------------------------------------------------------------------------
__global__ void __launch_bounds__(256) pair_rescue_kernel(const float* __restrict__ z,
                                                          const float* __restrict__ cb) {
    const int cnt  = g_pair_cnt;
    const int lane = threadIdx.x & 31;
    const int wpb  = blockDim.x >> 5;
    for (int i = blockIdx.x * wpb + (threadIdx.x >> 5); i < cnt; i += gridDim.x * wpb) {
        const int tok = g_pair[i];
        const int2 cd = g_pairc[i];
        const int b = tok >> 10, hw = tok & (HW - 1);
        const float* zp = z + b * (DIM * HW) + hw;
        float zl = zp[lane << 10];
        float zh = zp[(lane + 32) << 10];
        const float* c1 = cb + cd.x * DIM;
        const float* c2 = cb + cd.y * DIM;
        float d1 = fmaf(zh, c1[lane + 32], zl * c1[lane]);
        float d2 = fmaf(zh, c2[lane + 32], zl * c2[lane]);
#pragma unroll
        for (int o = 16; o > 0; o >>= 1) {
            d1 += __shfl_down_sync(0xffffffffu, d1, o);
            d2 += __shfl_down_sync(0xffffffffu, d2, o);
        }
        if (lane == 0) {
            float e1 = fmaf(-2.f, d1, g_cnorm[cd.x]);
            float e2 = fmaf(-2.f, d2, g_cnorm[cd.y]);
            int ch; float em;
            if (e2 < e1 || (e2 == e1 && cd.y < cd.x)) { ch = cd.y; em = e2; }
            else                                      { ch = cd.x; em = e1; }
            g_idx[tok] = ch;
            atomicAdd(&g_hist[ch], 1);
            atomicAdd(&g_losssum, g_pairn[i] + em);
        }
    }
}

// ---------------------------------------------------------------------------
// Full rescue (per-warp, latency-friendly for small counts): one warp per
// token; exact fp32 scan of all 1024 codes via float4 L2-resident loads.
// Also emits exact hist + loss for its tokens.
// ---------------------------------------------------------------------------
__global__ void __launch_bounds__(128) rescue_kernel(const float* __restrict__ z,
                                                     const float* __restrict__ cb) {
    const int nrs  = g_rescue_cnt;
    const int lane = threadIdx.x & 31;
    const int wpb  = blockDim.x >> 5;
    for (int i = blockIdx.x * wpb + (threadIdx.x >> 5); i < nrs; i += gridDim.x * wpb) {
        const int tok = g_rescue[i];
        const int b   = tok >> 10;
        const int hw  = tok & (HW - 1);
        const float* zp = z + b * (DIM * HW) + hw;
        float zr[DIM];
        float nv = 0.f;
#pragma unroll
        for (int c = 0; c < DIM; ++c) {
            zr[c] = zp[c << 10];
            nv = fmaf(zr[c], zr[c], nv);    // exact ||z||^2, ascending c
        }

        float best = 3.4e38f; int bidx = 0x7fffffff;
        for (int k = lane; k < KCODES; k += 32) {
            const float4* cr = (const float4*)(cb + k * DIM);
            float a = 0.f;
#pragma unroll
            for (int c4 = 0; c4 < 16; ++c4) {
                float4 v = cr[c4];
                a = fmaf(zr[4 * c4 + 0], v.x, a);
                a = fmaf(zr[4 * c4 + 1], v.y, a);
                a = fmaf(zr[4 * c4 + 2], v.z, a);
                a = fmaf(zr[4 * c4 + 3], v.w, a);
            }
            float s = fmaf(-2.f, a, g_cnorm[k]);
            if (s < best) { best = s; bidx = k; }
        }
#pragma unroll
        for (int o = 16; o > 0; o >>= 1) {
            float ob = __shfl_down_sync(0xffffffffu, best, o);
            int   oi = __shfl_down_sync(0xffffffffu, bidx, o);
            if (ob < best || (ob == best && oi < bidx)) { best = ob; bidx = oi; }
        }
        if (lane == 0) {
            g_idx[tok] = bidx;
            atomicAdd(&g_hist[bidx], 1);
            atomicAdd(&g_losssum, nv + best);
        }
    }
}

// ---------------------------------------------------------------------------
// Epilogue-lite: gather codebook -> NCHW out; block 0 emits scalars.
// ---------------------------------------------------------------------------
__global__ void __launch_bounds__(256) epilogue_kernel(const float* __restrict__ cb,
                                                       float* __restrict__ out,
                                                       const int* __restrict__ flg,
                                                       int write_scalars) {
    const int sub  = threadIdx.x >> 6;
    const int tpos = threadIdx.x & 63;
    const int n    = blockIdx.x * 64 + tpos;
    const int b    = n >> 10;
    const int hw   = n & (HW - 1);
    const int idx  = g_idx[n];
    const float4* cbr = (const float4*)(cb + idx * DIM) + sub * 4;
    const int base = b * (DIM * HW) + hw + (sub << 14);

    float4 q[4];
#pragma unroll
    for (int j = 0; j < 4; ++j) q[j] = __ldg(cbr + j);
#pragma unroll
    for (int j = 0; j < 4; ++j) {
        const int c = j * 4;
        out[base + ((c + 0) << 10)] = q[j].x;
        out[base + ((c + 1) << 10)] = q[j].y;
        out[base + ((c + 2) << 10)] = q[j].z;
        out[base + ((c + 3) << 10)] = q[j].w;
    }

    if (blockIdx.x == 0 && write_scalars) {
        float t = 0.f;
#pragma unroll
        for (int j = 0; j < 4; ++j) {
            int k = threadIdx.x * 4 + j;
            float e = (float)g_hist[k] * (1.f / (float)NTOK);
            t = fmaf(e, logf(e + 1e-10f), t);
        }
#pragma unroll
        for (int o = 16; o > 0; o >>= 1)
            t += __shfl_down_sync(0xffffffffu, t, o);
        __shared__ float red[8];
        if ((threadIdx.x & 31) == 0) red[threadIdx.x >> 5] = t;
        __syncthreads();
        if (threadIdx.x == 0) {
            float v = 0.f;
#pragma unroll
            for (int w = 0; w < 8; ++w) v += red[w];
            int fbits = *flg;
            float loss = (fbits != 0)
                       ? 1.25f * g_losssum * (1.f / (float)ZQ_ELEMS)
                       : 0.f;
            out[ZQ_ELEMS]     = loss;
            out[ZQ_ELEMS + 1] = expf(-v);
        }
    }
}

// ---------------------------------------------------------------------------
extern "C" void kernel_launch(void* const* d_in, const int* in_sizes, int n_in,
                              void* d_out, int out_size) {
    const float* z   = (const float*)d_in[0];
    const float* cb  = (const float*)d_in[1];
    const int*   flg = (const int*)d_in[3];
    float* out = (float*)d_out;

    prep_kernel<<<32, 32>>>(cb);
    argmin_mma_kernel<<<NTOK / 128, 256>>>(z);
    pair_rescue_kernel<<<148, 256>>>(z, cb);
    rescue_kernel<<<256, 128>>>(z, cb);
    epilogue_kernel<<<NTOK / 64, 256>>>(cb, out, flg,
                                        out_size >= ZQ_ELEMS + 2 ? 1 : 0);
}

// round 15
// speedup vs baseline: 1.3078x; 1.3078x over previous
#include <cuda_runtime.h>
#include <cuda_fp16.h>
#include <math.h>
#include <stdint.h>

// Problem constants
#define NB     64
#define DIM    64
#define HW     1024
#define NTOK   65536         // NB*HW
#define KCODES 1024
#define ZQ_ELEMS 4194304     // NB*DIM*HW
#define CHUNK  64            // codes per smem chunk (argmin)
#define NCHUNKS (KCODES / CHUNK)   // 16
#define EPS    0.065f
#define RT     8             // tokens per block in full rescue

// ---------------------------------------------------------------------------
// Device global scratch (no allocation allowed)
// ---------------------------------------------------------------------------
__device__ __align__(16) uint2 g_cbf[NCHUNKS * 8 * 4 * 32];   // fp16 fragments, 128 KB
__device__ __align__(16) float g_cbT[DIM * KCODES];           // transposed fp32, 256 KB
__device__ __align__(16) float g_cnorm[KCODES];
__device__ int   g_idx[NTOK];
__device__ int   g_rescue[NTOK];       // full-scan rescue list (3-way ambiguous)
__device__ int   g_rescue_cnt;
__device__ int   g_pair[NTOK];         // pair-rescue list (2-way ambiguous)
__device__ int2  g_pairc[NTOK];        // candidate indices {i1, i2}
__device__ float g_pairn[NTOK];        // exact ||z||^2
__device__ int   g_pair_cnt;
__device__ float g_losssum;
__device__ int   g_hist[KCODES];

// ---------------------------------------------------------------------------
// Helpers
// ---------------------------------------------------------------------------
__device__ __forceinline__ void mma16816_f16(float* c, const uint32_t* a,
                                             uint32_t b0, uint32_t b1) {
    asm volatile(
        "mma.sync.aligned.m16n8k16.row.col.f32.f16.f16.f32 "
        "{%0,%1,%2,%3}, {%4,%5,%6,%7}, {%8,%9}, {%0,%1,%2,%3};"
        : "+f"(c[0]), "+f"(c[1]), "+f"(c[2]), "+f"(c[3])
        : "r"(a[0]), "r"(a[1]), "r"(a[2]), "r"(a[3]), "r"(b0), "r"(b1));
}
__device__ __forceinline__ uint32_t pack_h2(float v0, float v1) {
    __half2 h = __floats2half2_rn(v0, v1);
    return *(uint32_t*)&h;
}
__device__ __forceinline__ uint32_t smem_u32(const void* p) {
    uint32_t a;
    asm("{ .reg .u64 t; cvta.to.shared.u64 t, %1; cvt.u32.u64 %0, t; }"
        : "=r"(a) : "l"(p));
    return a;
}
__device__ __forceinline__ void cp16(uint32_t dst, const void* src) {
    asm volatile("cp.async.cg.shared.global [%0], [%1], 16;"
                 :: "r"(dst), "l"(src));
}
#define CP_COMMIT() asm volatile("cp.async.commit_group;" ::: "memory")
#define CP_WAIT0()  asm volatile("cp.async.wait_group 0;" ::: "memory")

// top-3 tracker (strict < and ascending code order -> first-occurrence ties)
__device__ __forceinline__ void upd3(float s, int code,
                                     float& s1, int& i1,
                                     float& s2, int& i2, float& s3) {
    if (s < s3) {
        if (s < s2) {
            s3 = s2;
            if (s < s1) { s2 = s1; i2 = i1; s1 = s; i1 = code; }
            else        { s2 = s;  i2 = code; }
        } else s3 = s;
    }
}
__device__ __forceinline__ bool lexless(float v, int i, float w, int j) {
    return v < w || (v == w && i < j);
}

// ---------------------------------------------------------------------------
// Prep: fp16 fragment codebook + transposed fp32 codebook, ||c||^2, counters
// ---------------------------------------------------------------------------
__global__ void prep_kernel(const float* __restrict__ cb) {
    int k = blockIdx.x * blockDim.x + threadIdx.x;
    if (k >= KCODES) return;
    float v[DIM];
    float s = 0.f;
#pragma unroll
    for (int c = 0; c < DIM; ++c) {
        v[c] = cb[k * DIM + c];
        s = fmaf(v[c], v[c], s);
        g_cbT[c * KCODES + k] = v[c];
    }
    g_cnorm[k] = s;
    g_hist[k]  = 0;
    if (k == 0) { g_losssum = 0.f; g_rescue_cnt = 0; g_pair_cnt = 0; }

    const int chunk = k >> 6;
    const int n8    = (k & 63) >> 3;
    const int g     = k & 7;
#pragma unroll
    for (int ks = 0; ks < 4; ++ks) {
#pragma unroll
        for (int t4 = 0; t4 < 4; ++t4) {
            int d0 = ks * 16 + t4 * 2;
            int idx = ((chunk * 8 + n8) * 4 + ks) * 32 + g * 4 + t4;
            g_cbf[idx] = make_uint2(pack_h2(v[d0],     v[d0 + 1]),
                                    pack_h2(v[d0 + 8], v[d0 + 9]));
        }
    }
}

// ---------------------------------------------------------------------------
// fp16 HMMA argmin: 8 warps x 16 tokens; 1-term fp16 mma.sync (fp32 accum).
// Tracks top-3 (+ ||z||^2). Unflagged -> hist/loss here. 2-way ambiguous ->
// pair rescue {i1,i2}. 3-way ambiguous -> full-scan rescue.
// ---------------------------------------------------------------------------
#define SMCN_F   0
#define SMBUF(b) (4096 + (b) * 8192)
#define SM_BYTES (4096 + 2 * 8192)

__global__ void __launch_bounds__(256) argmin_mma_kernel(const float* __restrict__ z) {
    __shared__ __align__(16) char smem[SM_BYTES];
    const uint32_t smb = smem_u32(smem);
    const int tid  = threadIdx.x;
    const int wid  = tid >> 5;
    const int lane = tid & 31;
    const int g    = lane >> 2;
    const int t4   = lane & 3;

    {
        float4* dst = (float4*)(smem + SMCN_F);
        const float4* src = (const float4*)g_cnorm;
        dst[tid] = src[tid];
    }

    const int wbase = blockIdx.x * 128 + wid * 16;
    const int b     = wbase >> 10;
    const int hw0   = (wbase & (HW - 1)) + g;
    const float* zb = z + b * (DIM * HW);
    uint32_t Ah[16];
    float n0 = 0.f, n1 = 0.f;        // partial ||z||^2 for tokens g, g+8
#pragma unroll
    for (int ks = 0; ks < 4; ++ks) {
        int c0 = ks * 16 + t4 * 2;
        float a0 = zb[(c0)     * HW + hw0],     a1 = zb[(c0 + 1) * HW + hw0];
        float b0 = zb[(c0)     * HW + hw0 + 8], b1 = zb[(c0 + 1) * HW + hw0 + 8];
        float a2 = zb[(c0 + 8) * HW + hw0],     a3 = zb[(c0 + 9) * HW + hw0];
        float b2 = zb[(c0 + 8) * HW + hw0 + 8], b3 = zb[(c0 + 9) * HW + hw0 + 8];
        n0 = fmaf(a0, a0, n0); n0 = fmaf(a1, a1, n0);
        n0 = fmaf(a2, a2, n0); n0 = fmaf(a3, a3, n0);
        n1 = fmaf(b0, b0, n1); n1 = fmaf(b1, b1, n1);
        n1 = fmaf(b2, b2, n1); n1 = fmaf(b3, b3, n1);
        Ah[ks * 4 + 0] = pack_h2(a0, a1);
        Ah[ks * 4 + 1] = pack_h2(b0, b1);
        Ah[ks * 4 + 2] = pack_h2(a2, a3);
        Ah[ks * 4 + 3] = pack_h2(b2, b3);
    }

    {
        const char* src = (const char*)g_cbf;
        uint32_t d = smb + SMBUF(0);
#pragma unroll
        for (int i = 0; i < 2; ++i)
            cp16(d + tid * 16 + i * 4096, src + tid * 16 + i * 4096);
        CP_COMMIT();
    }

    float s1a = 3.4e38f, s2a = 3.4e38f, s3a = 3.4e38f; int i1a = 0, i2a = 0;
    float s1b = 3.4e38f, s2b = 3.4e38f, s3b = 3.4e38f; int i1b = 0, i2b = 0;

    for (int t = 0; t < NCHUNKS; ++t) {
        const int buf = t & 1;
        CP_WAIT0();
        __syncthreads();

        if (t + 1 < NCHUNKS) {
            const char* src = (const char*)g_cbf + (t + 1) * 8192;
            uint32_t d = smb + SMBUF(1 - buf);
#pragma unroll
            for (int i = 0; i < 2; ++i)
                cp16(d + tid * 16 + i * 4096, src + tid * 16 + i * 4096);
            CP_COMMIT();
        }

        const uint2* bq = (const uint2*)(smem + SMBUF(buf));
        const float* cn = (const float*)(smem + SMCN_F);

#pragma unroll
        for (int n8 = 0; n8 < 8; ++n8) {
            uint2 Bf[4];
#pragma unroll
            for (int ks = 0; ks < 4; ++ks)
                Bf[ks] = bq[(n8 * 4 + ks) * 32 + lane];
            float ae[4] = {0.f, 0.f, 0.f, 0.f};
            float ao[4] = {0.f, 0.f, 0.f, 0.f};
            mma16816_f16(ae, &Ah[0],  Bf[0].x, Bf[0].y);
            mma16816_f16(ao, &Ah[4],  Bf[1].x, Bf[1].y);
            mma16816_f16(ae, &Ah[8],  Bf[2].x, Bf[2].y);
            mma16816_f16(ao, &Ah[12], Bf[3].x, Bf[3].y);

            const int code = t * CHUNK + n8 * 8 + t4 * 2;
            float2 cnv = *(const float2*)(cn + code);
            float s;
            s = fmaf(-2.f, ae[0] + ao[0], cnv.x); upd3(s, code,     s1a, i1a, s2a, i2a, s3a);
            s = fmaf(-2.f, ae[1] + ao[1], cnv.y); upd3(s, code + 1, s1a, i1a, s2a, i2a, s3a);
            s = fmaf(-2.f, ae[2] + ao[2], cnv.x); upd3(s, code,     s1b, i1b, s2b, i2b, s3b);
            s = fmaf(-2.f, ae[3] + ao[3], cnv.y); upd3(s, code + 1, s1b, i1b, s2b, i2b, s3b);
        }
        __syncthreads();
    }

    // Reduce top-3 (lex) and norms across the 4 lanes of each quad
#pragma unroll
    for (int off = 1; off <= 2; off <<= 1) {
        float ob1, ob2, ob3; int oj1, oj2;
        // token a
        ob1 = __shfl_xor_sync(0xffffffffu, s1a, off);
        ob2 = __shfl_xor_sync(0xffffffffu, s2a, off);
        ob3 = __shfl_xor_sync(0xffffffffu, s3a, off);
        oj1 = __shfl_xor_sync(0xffffffffu, i1a, off);
        oj2 = __shfl_xor_sync(0xffffffffu, i2a, off);
        {
            float r1, r2, r3; int q1, q2;
            if (lexless(ob1, oj1, s1a, i1a)) {
                r1 = ob1; q1 = oj1;
                if (lexless(s1a, i1a, ob2, oj2)) { r2 = s1a; q2 = i1a; r3 = fminf(s2a, ob2); }
                else                             { r2 = ob2; q2 = oj2; r3 = fminf(ob3, s1a); }
            } else {
                r1 = s1a; q1 = i1a;
                if (lexless(ob1, oj1, s2a, i2a)) { r2 = ob1; q2 = oj1; r3 = fminf(s2a, ob2); }
                else                             { r2 = s2a; q2 = i2a; r3 = fminf(s3a, ob1); }
            }
            s1a = r1; i1a = q1; s2a = r2; i2a = q2; s3a = r3;
        }
        // token b
        ob1 = __shfl_xor_sync(0xffffffffu, s1b, off);
        ob2 = __shfl_xor_sync(0xffffffffu, s2b, off);
        ob3 = __shfl_xor_sync(0xffffffffu, s3b, off);
        oj1 = __shfl_xor_sync(0xffffffffu, i1b, off);
        oj2 = __shfl_xor_sync(0xffffffffu, i2b, off);
        {
            float r1, r2, r3; int q1, q2;
            if (lexless(ob1, oj1, s1b, i1b)) {
                r1 = ob1; q1 = oj1;
                if (lexless(s1b, i1b, ob2, oj2)) { r2 = s1b; q2 = i1b; r3 = fminf(s2b, ob2); }
                else                             { r2 = ob2; q2 = oj2; r3 = fminf(ob3, s1b); }
            } else {
                r1 = s1b; q1 = i1b;
                if (lexless(ob1, oj1, s2b, i2b)) { r2 = ob1; q2 = oj1; r3 = fminf(s2b, ob2); }
                else                             { r2 = s2b; q2 = i2b; r3 = fminf(s3b, ob1); }
            }
            s1b = r1; i1b = q1; s2b = r2; i2b = q2; s3b = r3;
        }
        n0 += __shfl_xor_sync(0xffffffffu, n0, off);
        n1 += __shfl_xor_sync(0xffffffffu, n1, off);
    }

    float contrib = 0.f;
    if (t4 == 0) {
        const int tok0 = wbase + g;
        const int tok1 = wbase + g + 8;
        if (s2a - s1a >= EPS) {
            g_idx[tok0] = i1a;
            atomicAdd(&g_hist[i1a], 1);
            contrib += n0 + s1a;
        } else if (s3a - s1a >= EPS) {
            int s = atomicAdd(&g_pair_cnt, 1);
            g_pair[s] = tok0; g_pairc[s] = make_int2(i1a, i2a); g_pairn[s] = n0;
        } else {
            int s = atomicAdd(&g_rescue_cnt, 1); g_rescue[s] = tok0;
        }
        if (s2b - s1b >= EPS) {
            g_idx[tok1] = i1b;
            atomicAdd(&g_hist[i1b], 1);
            contrib += n1 + s1b;
        } else if (s3b - s1b >= EPS) {
            int s = atomicAdd(&g_pair_cnt, 1);
            g_pair[s] = tok1; g_pairc[s] = make_int2(i1b, i2b); g_pairn[s] = n1;
        } else {
            int s = atomicAdd(&g_rescue_cnt, 1); g_rescue[s] = tok1;
        }
    }
#pragma unroll
    for (int o = 16; o > 0; o >>= 1)
        contrib += __shfl_down_sync(0xffffffffu, contrib, o);
    if (lane == 0) atomicAdd(&g_losssum, contrib);
}

// ---------------------------------------------------------------------------
// Pair rescue: exact fp32 scoring of 2 candidate codes; one warp per token.
// ---------------------------------------------------------------------------
__global__ void __launch_bounds__(256) pair_rescue_kernel(const float* __restrict__ z,
                                                          const float* __restrict__ cb) {
    const int cnt  = g_pair_cnt;
    const int lane = threadIdx.x & 31;
    const int wpb  = blockDim.x >> 5;
    for (int i = blockIdx.x * wpb + (threadIdx.x >> 5); i < cnt; i += gridDim.x * wpb) {
        const int tok = g_pair[i];
        const int2 cd = g_pairc[i];
        const int b = tok >> 10, hw = tok & (HW - 1);
        const float* zp = z + b * (DIM * HW) + hw;
        float zl = zp[lane << 10];
        float zh = zp[(lane + 32) << 10];
        const float* c1 = cb + cd.x * DIM;
        const float* c2 = cb + cd.y * DIM;
        float d1 = fmaf(zh, c1[lane + 32], zl * c1[lane]);
        float d2 = fmaf(zh, c2[lane + 32], zl * c2[lane]);
#pragma unroll
        for (int o = 16; o > 0; o >>= 1) {
            d1 += __shfl_down_sync(0xffffffffu, d1, o);
            d2 += __shfl_down_sync(0xffffffffu, d2, o);
        }
        if (lane == 0) {
            float e1 = fmaf(-2.f, d1, g_cnorm[cd.x]);
            float e2 = fmaf(-2.f, d2, g_cnorm[cd.y]);
            int ch; float em;
            if (e2 < e1 || (e2 == e1 && cd.y < cd.x)) { ch = cd.y; em = e2; }
            else                                      { ch = cd.x; em = e1; }
            g_idx[tok] = ch;
            atomicAdd(&g_hist[ch], 1);
            atomicAdd(&g_losssum, g_pairn[i] + em);
        }
    }
}

// ---------------------------------------------------------------------------
// Full rescue: 8 tokens/block (one warp each), transposed codebook streamed
// through smem as 16 double-buffered cp.async chunks of 64 codes. Exact fp32,
// ascending-c fmaf chains, lex tie-break. Emits hist + exact loss.
// smem: 2KB z + 2x16KB chunks = 34KB
// ---------------------------------------------------------------------------
__global__ void __launch_bounds__(256) rescue_kernel(const float* __restrict__ z) {
    __shared__ __align__(16) float smZ[RT][DIM];        // 2 KB
    __shared__ __align__(16) float smC[2][DIM][64];     // 32 KB
    const int cnt  = g_rescue_cnt;
    const int tid  = threadIdx.x;
    const int wid  = tid >> 5;
    const int lane = tid & 31;
    const uint32_t smcb = smem_u32(&smC[0][0][0]);

    for (int base = blockIdx.x * RT; base < cnt; base += gridDim.x * RT) {
        __syncthreads();   // smZ/smC reuse across base iterations
        // Stage RT tokens' z vectors (2 floats per thread; clamped gather)
#pragma unroll
        for (int j = 0; j < 2; ++j) {
            int li = tid * 2 + j;              // 0..511
            int t  = li >> 6;
            int c  = li & 63;
            int gi = base + t;
            int tok = g_rescue[gi < cnt ? gi : cnt - 1];
            int bb = tok >> 10, hw = tok & (HW - 1);
            smZ[t][c] = z[bb * (DIM * HW) + c * HW + hw];
        }
        // Prefetch chunk 0: 64 rows x 64 floats = 1024 float4, 4 per thread
#pragma unroll
        for (int i = 0; i < 4; ++i) {
            int li = tid + i * 256;
            int r  = li >> 4;                  // channel row
            int cc = li & 15;                  // float4 col within chunk
            cp16(smcb + (uint32_t)li * 16u,
                 g_cbT + r * KCODES + cc * 4);
        }
        CP_COMMIT();

        float best = 3.4e38f; int bidx = 0;

        for (int ch = 0; ch < 16; ++ch) {
            const int buf = ch & 1;
            CP_WAIT0();
            __syncthreads();                   // chunk ch ready; prev compute done

            if (ch + 1 < 16) {                 // prefetch ch+1 into other buffer
#pragma unroll
                for (int i = 0; i < 4; ++i) {
                    int li = tid + i * 256;
                    int r  = li >> 4;
                    int cc = li & 15;
                    cp16(smcb + (uint32_t)(1 - buf) * 16384u + (uint32_t)li * 16u,
                         g_cbT + r * KCODES + (ch + 1) * 64 + cc * 4);
                }
                CP_COMMIT();
            }

            // warp wid scans chunk for its token: 2 codes per lane
            const float* zt = smZ[wid];
            float a0 = 0.f, a1 = 0.f;
#pragma unroll
            for (int c = 0; c < DIM; ++c) {
                float zc = zt[c];                                    // broadcast
                float2 cv = *(const float2*)&smC[buf][c][lane * 2];  // conflict-free
                a0 = fmaf(zc, cv.x, a0);
                a1 = fmaf(zc, cv.y, a1);
            }
            const int k0 = ch * 64 + lane * 2;
            float2 cn = *(const float2*)&g_cnorm[k0];
            float s;
            s = fmaf(-2.f, a0, cn.x); if (s < best) { best = s; bidx = k0;     }
            s = fmaf(-2.f, a1, cn.y); if (s < best) { best = s; bidx = k0 + 1; }
        }

        // lex reduce over lanes
#pragma unroll
        for (int o = 16; o > 0; o >>= 1) {
            float ob = __shfl_down_sync(0xffffffffu, best, o);
            int   oi = __shfl_down_sync(0xffffffffu, bidx, o);
            if (ob < best || (ob == best && oi < bidx)) { best = ob; bidx = oi; }
        }
        // exact ||z||^2 (lane-parallel + reduce)
        const float* zt = smZ[wid];
        float nv = zt[lane] * zt[lane] + zt[lane + 32] * zt[lane + 32];
#pragma unroll
        for (int o = 16; o > 0; o >>= 1)
            nv += __shfl_down_sync(0xffffffffu, nv, o);
        if (lane == 0) {
            int gi = base + wid;
            if (gi < cnt) {
                int tok = g_rescue[gi];
                g_idx[tok] = bidx;
                atomicAdd(&g_hist[bidx], 1);
                atomicAdd(&g_losssum, nv + best);
            }
        }
    }
}

// ---------------------------------------------------------------------------
// Epilogue-lite: gather codebook -> NCHW out; block 0 emits scalars.
// ---------------------------------------------------------------------------
__global__ void __launch_bounds__(256) epilogue_kernel(const float* __restrict__ cb,
                                                       float* __restrict__ out,
                                                       const int* __restrict__ flg,
                                                       int write_scalars) {
    const int sub  = threadIdx.x >> 6;
    const int tpos = threadIdx.x & 63;
    const int n    = blockIdx.x * 64 + tpos;
    const int b    = n >> 10;
    const int hw   = n & (HW - 1);
    const int idx  = g_idx[n];
    const float4* cbr = (const float4*)(cb + idx * DIM) + sub * 4;
    const int base = b * (DIM * HW) + hw + (sub << 14);

    float4 q[4];
#pragma unroll
    for (int j = 0; j < 4; ++j) q[j] = __ldg(cbr + j);
#pragma unroll
    for (int j = 0; j < 4; ++j) {
        const int c = j * 4;
        out[base + ((c + 0) << 10)] = q[j].x;
        out[base + ((c + 1) << 10)] = q[j].y;
        out[base + ((c + 2) << 10)] = q[j].z;
        out[base + ((c + 3) << 10)] = q[j].w;
    }

    if (blockIdx.x == 0 && write_scalars) {
        float t = 0.f;
#pragma unroll
        for (int j = 0; j < 4; ++j) {
            int k = threadIdx.x * 4 + j;
            float e = (float)g_hist[k] * (1.f / (float)NTOK);
            t = fmaf(e, logf(e + 1e-10f), t);
        }
#pragma unroll
        for (int o = 16; o > 0; o >>= 1)
            t += __shfl_down_sync(0xffffffffu, t, o);
        __shared__ float red[8];
        if ((threadIdx.x & 31) == 0) red[threadIdx.x >> 5] = t;
        __syncthreads();
        if (threadIdx.x == 0) {
            float v = 0.f;
#pragma unroll
            for (int w = 0; w < 8; ++w) v += red[w];
            int fbits = *flg;
            float loss = (fbits != 0)
                       ? 1.25f * g_losssum * (1.f / (float)ZQ_ELEMS)
                       : 0.f;
            out[ZQ_ELEMS]     = loss;
            out[ZQ_ELEMS + 1] = expf(-v);
        }
    }
}

// ---------------------------------------------------------------------------
extern "C" void kernel_launch(void* const* d_in, const int* in_sizes, int n_in,
                              void* d_out, int out_size) {
    const float* z   = (const float*)d_in[0];
    const float* cb  = (const float*)d_in[1];
    const int*   flg = (const int*)d_in[3];
    float* out = (float*)d_out;

    prep_kernel<<<32, 32>>>(cb);
    argmin_mma_kernel<<<NTOK / 128, 256>>>(z);
    pair_rescue_kernel<<<148, 256>>>(z, cb);
    rescue_kernel<<<512, 256>>>(z);
    epilogue_kernel<<<NTOK / 64, 256>>>(cb, out, flg,
                                        out_size >= ZQ_ELEMS + 2 ? 1 : 0);
}